// round 3
// baseline (speedup 1.0000x reference)
#include <cuda_runtime.h>
#include <stdint.h>

// Fixed problem shapes
#define TT 5
#define BB 8
#define HH 128
#define WW 128
#define HW (HH*WW)          // 16384
#define C1 3
#define C2 64

// ---------------- static scratch ----------------
__device__ __align__(16) uint32_t g_s1b[(size_t)TT*BB*C2*HH*4];  // spike bitplanes (5.2 MB)
__device__ __align__(16) float    g_y2[(size_t)TT*BB*C2*HW];     // conv2 output (168 MB)
__device__ __align__(16) float    g_w2t[9*C2*C2];                // W2 as [tap][ic][oc]

// ---------------- K0: W2 [oc][ic][tap] -> [tap][ic][oc] ----------------
__global__ void k0_transpose_w2(const float* __restrict__ W2) {
    int i = blockIdx.x * 256 + threadIdx.x;
    if (i < 9*C2*C2) {
        int oc  = i / (C2*9);
        int r   = i % (C2*9);
        int ic  = r / 9;
        int tap = r % 9;
        g_w2t[(tap*C2 + ic)*C2 + oc] = W2[i];
    }
}

// ---------------- K1: conv1 (3->64, 3x3, pad1) + 5-step LIF1, spikes as bitplanes ----------------
// tile 32x8 pixels, block 256 (px = tid&31 so a warp == one 32-px output word)
__global__ __launch_bounds__(256) void k1_conv1_lif1(
    const float* __restrict__ x,     // [B,3,128,128]
    const float* __restrict__ W1,    // [64,3,3,3]
    const float* __restrict__ b1,
    const float* __restrict__ tau1p)
{
    __shared__ __align__(16) float xs[C1][10][36];   // 34 used + pad
    __shared__ __align__(16) float ws[27][C2];       // [(dy*3+dx)*3 + c][oc]
    __shared__ float bs[C2];

    const int tid = threadIdx.x;
    const int tx = blockIdx.x & 3;        // 0..3  (32-px columns)
    const int ty = blockIdx.x >> 2;       // 0..15 (8-row bands)
    const int b  = blockIdx.y;

    // weights: reorder to tap-major, channel-minor
    for (int i = tid; i < C2*27; i += 256) {
        int o = i / 27, r = i % 27;
        int c = r / 9, t9 = r % 9;        // t9 = dy*3+dx
        ws[t9*3 + c][o] = W1[i];
    }
    if (tid < C2) bs[tid] = b1[tid];

    // input tile with halo (34 x 10 per channel)
    for (int i = tid; i < C1*10*34; i += 256) {
        int c = i / 340, r = i % 340, y = r / 34, xc = r % 34;
        int gy = ty*8 - 1 + y, gx = tx*32 - 1 + xc;
        float v = 0.f;
        if ((unsigned)gy < (unsigned)HH && (unsigned)gx < (unsigned)WW)
            v = x[((size_t)b*C1 + c)*HW + gy*WW + gx];
        xs[c][y][xc] = v;
    }
    __syncthreads();

    const int px = tid & 31, py = tid >> 5;

    float acc[C2];
    #pragma unroll
    for (int o = 0; o < C2; ++o) acc[o] = 0.f;

    // accumulation order per output element: (dy, dx, c) with c innermost
    #pragma unroll
    for (int dy = 0; dy < 3; ++dy)
        #pragma unroll
        for (int dx = 0; dx < 3; ++dx)
            #pragma unroll
            for (int c = 0; c < C1; ++c) {
                float xv = xs[c][py+dy][px+dx];
                const float4* wp = (const float4*)&ws[(dy*3+dx)*3 + c][0];
                #pragma unroll
                for (int q = 0; q < 16; ++q) {
                    float4 w = wp[q];
                    acc[q*4+0] = fmaf(w.x, xv, acc[q*4+0]);
                    acc[q*4+1] = fmaf(w.y, xv, acc[q*4+1]);
                    acc[q*4+2] = fmaf(w.z, xv, acc[q*4+2]);
                    acc[q*4+3] = fmaf(w.w, xv, acc[q*4+3]);
                }
            }

    float tau = tau1p[0];
    tau = fminf(fmaxf(tau, 0.5f), 5.0f);
    const float it = 1.0f / tau;

    const int gy = ty*8 + py;

    #pragma unroll
    for (int o = 0; o < C2; ++o) {
        const float xo = __fadd_rn(acc[o], bs[o]);   // bias after conv (matches y = conv + b)
        float v = 0.f;
        #pragma unroll
        for (int t = 0; t < TT; ++t) {
            v = __fadd_rn(v, __fmul_rn(it, __fadd_rn(xo, -v)));
            int s = (__fadd_rn(v, -0.1f) >= 0.f);
            v = s ? 0.f : fminf(fmaxf(v, -2.f), 2.f);
            unsigned w = __ballot_sync(0xffffffffu, s);
            if (px == 0)
                g_s1b[(((size_t)t*BB + b)*C2 + o)*HH*4 + (size_t)gy*4 + tx] = w;
        }
    }
}

// ---------------- K2: conv2 (64->64, 3x3, pad1) on spike bits ----------------
// accumulation order per output: (dy, dx, ic) with ic innermost (tap outer loop)
// grid (64 tiles of 16x16, 40 tb), block 256; each thread 8oc x 8px
__global__ __launch_bounds__(256, 2) void k2_conv2(const float* __restrict__ b2)
{
    __shared__ uint32_t sb[C2][18];                  // 18-bit rows of spike tile (+halo)
    __shared__ __align__(16) float sw[C2][C2];       // [ic][oc] for the current tap
    __shared__ float sbias[C2];

    const int tid = threadIdx.x;
    const int t = blockIdx.y >> 3, b = blockIdx.y & 7;
    const int tx = blockIdx.x & 7, ty = blockIdx.x >> 3;

    const int lane = tid & 31, ocg = tid >> 5;
    const int py = lane >> 1, pxb = (lane & 1) * 8;

    if (tid < C2) sbias[tid] = b2[tid];

    const uint32_t* src = g_s1b + (size_t)(t*BB + b)*C2*HH*4;

    // build 18-bit spike rows for all 64 ic (bit k = input x = tx*16 - 1 + k)
    for (int i = tid; i < C2*18; i += 256) {
        int ic = i / 18, y = i % 18;
        int gy = ty*16 - 1 + y;
        uint32_t val = 0;
        if ((unsigned)gy < (unsigned)HH) {
            int g0 = tx*16 - 1;
            int w0 = g0 >> 5;                 // -1 only when tx==0
            int off = g0 & 31;
            const uint32_t* rowp = src + ((size_t)ic*HH + gy)*4;
            uint32_t lo = (w0 >= 0) ? rowp[w0] : 0u;
            uint32_t hi = (w0 + 1 <= 3) ? rowp[w0 + 1] : 0u;
            val = __funnelshift_r(lo, hi, off);
        }
        sb[ic][y] = val;
    }

    float acc[64];
    #pragma unroll
    for (int i = 0; i < 64; ++i) acc[i] = 0.f;

    for (int tap = 0; tap < 9; ++tap) {
        __syncthreads();
        // stream this tap's [ic][oc] weight slab (16 KB)
        {
            const float4* wsrc = (const float4*)(g_w2t + (size_t)tap*C2*C2);
            float4* wdst = (float4*)&sw[0][0];
            for (int i = tid; i < C2*C2/4; i += 256) wdst[i] = wsrc[i];
        }
        __syncthreads();

        const int dy = tap / 3, dx = tap % 3;
        const int yidx = py + dy;
        const int sh = pxb + dx;

        #pragma unroll 4
        for (int ic = 0; ic < C2; ++ic) {
            uint32_t bbits = sb[ic][yidx] >> sh;
            const float4* wp = (const float4*)&sw[ic][ocg*8];
            float4 wa = wp[0], wb = wp[1];
            float wv[8] = {wa.x, wa.y, wa.z, wa.w, wb.x, wb.y, wb.z, wb.w};

            float sf[8];
            #pragma unroll
            for (int j = 0; j < 8; ++j)
                sf[j] = __uint_as_float(((bbits >> j) & 1u) * 0x3f800000u);

            #pragma unroll
            for (int o = 0; o < 8; ++o) {
                float w = wv[o];
                #pragma unroll
                for (int j = 0; j < 8; ++j)
                    acc[o*8 + j] = fmaf(w, sf[j], acc[o*8 + j]);
            }
        }
    }

    // epilogue: bias after conv, vectorized store
    float* ybase = g_y2 + ((size_t)(t*BB + b)*C2 + ocg*8)*HW
                 + (size_t)(ty*16 + py)*WW + tx*16 + pxb;
    #pragma unroll
    for (int o = 0; o < 8; ++o) {
        float bb = sbias[ocg*8 + o];
        float4 r0 = make_float4(__fadd_rn(acc[o*8+0],bb), __fadd_rn(acc[o*8+1],bb),
                                __fadd_rn(acc[o*8+2],bb), __fadd_rn(acc[o*8+3],bb));
        float4 r1 = make_float4(__fadd_rn(acc[o*8+4],bb), __fadd_rn(acc[o*8+5],bb),
                                __fadd_rn(acc[o*8+6],bb), __fadd_rn(acc[o*8+7],bb));
        *(float4*)(ybase + (size_t)o*HW)     = r0;
        *(float4*)(ybase + (size_t)o*HW + 4) = r1;
    }
}

// ---------------- K3: LIF2 (sequential t) + head conv (64->3, 1x1) ----------------
__global__ __launch_bounds__(256) void k3_lif2_head(
    const float* __restrict__ Wh,    // [3,64]
    const float* __restrict__ bh,
    const float* __restrict__ tau2p,
    float* __restrict__ out)         // [T,B,3,128,128]
{
    __shared__ float wh_s[3][C2];
    __shared__ float bh_s[3];
    const int tid = threadIdx.x;
    for (int i = tid; i < 3*C2; i += 256) wh_s[i / C2][i % C2] = Wh[i];
    if (tid < 3) bh_s[tid] = bh[tid];
    __syncthreads();

    const int idx = blockIdx.x * 256 + tid;
    const int b = idx >> 14;
    const int p = idx & (HW - 1);

    float tau = tau2p[0];
    tau = fminf(fmaxf(tau, 0.5f), 5.0f);
    const float it = 1.0f / tau;

    float v[C2];
    #pragma unroll
    for (int c = 0; c < C2; ++c) v[c] = 0.f;

    #pragma unroll
    for (int t = 0; t < TT; ++t) {
        const float* yb = g_y2 + ((size_t)t*BB + b)*C2*HW + p;
        float o0 = 0.f, o1 = 0.f, o2 = 0.f;
        #pragma unroll
        for (int c = 0; c < C2; ++c) {
            float xx = yb[(size_t)c*HW];
            float vv = __fadd_rn(v[c], __fmul_rn(it, __fadd_rn(xx, -v[c])));
            int s = (__fadd_rn(vv, -0.1f) >= 0.f);
            v[c] = s ? 0.f : fminf(fmaxf(vv, -2.f), 2.f);
            if (s) {                       // adding only nonzero products: exact
                o0 = __fadd_rn(o0, wh_s[0][c]);
                o1 = __fadd_rn(o1, wh_s[1][c]);
                o2 = __fadd_rn(o2, wh_s[2][c]);
            }
        }
        size_t ob = ((size_t)(t*BB + b)*3)*HW + p;
        out[ob]        = __fadd_rn(o0, bh_s[0]);
        out[ob +  HW]  = __fadd_rn(o1, bh_s[1]);
        out[ob + 2*HW] = __fadd_rn(o2, bh_s[2]);
    }
}

// ---------------- launch ----------------
extern "C" void kernel_launch(void* const* d_in, const int* in_sizes, int n_in,
                              void* d_out, int out_size)
{
    const float* lr_lab = (const float*)d_in[0];
    const float* W1     = (const float*)d_in[1];
    const float* b1     = (const float*)d_in[2];
    const float* tau1   = (const float*)d_in[3];
    const float* W2     = (const float*)d_in[4];
    const float* b2     = (const float*)d_in[5];
    const float* tau2   = (const float*)d_in[6];
    const float* Wh     = (const float*)d_in[7];
    const float* bh     = (const float*)d_in[8];
    float* out = (float*)d_out;

    k0_transpose_w2<<<(9*C2*C2 + 255)/256, 256>>>(W2);
    k1_conv1_lif1<<<dim3(64, BB), 256>>>(lr_lab, W1, b1, tau1);
    k2_conv2<<<dim3(64, TT*BB), 256>>>(b2);
    k3_lif2_head<<<(BB*HW)/256, 256>>>(Wh, bh, tau2, out);
}